// round 3
// baseline (speedup 1.0000x reference)
#include <cuda_runtime.h>

// Problem constants
#define Bc 2
#define Sc 2048
#define Dc 1024
#define Hc 16
#define DKc 64
#define Mc (Bc*Sc)   // 4096

// ---------------- scratch (no allocations allowed) ----------------
__device__ float g_Q[Bc*Hc*Sc*DKc];   // [B,H,S,DK]
__device__ float g_K[Bc*Hc*Sc*DKc];
__device__ float g_V[Bc*Hc*Sc*DKc];
__device__ float g_ctx[Mc*Dc];        // [B,S,D]
__device__ float g_pm[Bc*Sc];         // expanded padding mask (1.0 = masked)
__device__ int   g_mask_mode;         // 0=byte, 1=int32, 2=float32

// ---------------- padding-mask dtype sniffing ----------------
// Reads the first 1024 u32 words (= 4096 bytes, safe for all candidate dtypes).
// bool-byte mask: words contain byte patterns like 0x00010001 -> >1 with prob ~1.
// int32 0/1 mask: all words in {0,1}. float32 0/1 mask: all words in {0,0x3F800000}.
__global__ void detect_mask_k(const unsigned int* __restrict__ mm) {
    __shared__ int okInt, okFloat;
    if (threadIdx.x == 0) { okInt = 1; okFloat = 1; }
    __syncthreads();
    for (int i = threadIdx.x; i < 1024; i += blockDim.x) {
        unsigned int v = mm[i];
        if (v > 1u) okInt = 0;
        if (v != 0u && v != 0x3F800000u) okFloat = 0;
    }
    __syncthreads();
    if (threadIdx.x == 0)
        g_mask_mode = okInt ? 1 : (okFloat ? 2 : 0);
}

__global__ void expand_mask_k(const void* __restrict__ mraw) {
    int i = blockIdx.x * blockDim.x + threadIdx.x;
    if (i >= Bc * Sc) return;
    int mode = g_mask_mode;
    float v;
    if (mode == 1)       v = (((const int*)mraw)[i] != 0) ? 1.f : 0.f;
    else if (mode == 2)  v = (((const float*)mraw)[i] != 0.f) ? 1.f : 0.f;
    else                 v = (((const unsigned char*)mraw)[i] != 0) ? 1.f : 0.f;
    g_pm[i] = v;
}

// ---------------- fp32 SGEMM 128x128x8, 8x8 microtile, 256 threads ----------------
// LAYOUT 0: C[m, n] row-major [Mc, Dc]
// LAYOUT 1: C stored as [B, H, S, DK]  (n = h*64 + dk, m = b*Sc + s)
template<int LAYOUT>
__device__ __forceinline__ void gemm_body(
    const float* __restrict__ X, const float* __restrict__ W,
    const float* __restrict__ bias, float* __restrict__ C,
    float (*As)[128], float (*Bs)[128])
{
    const int tid = threadIdx.x;
    const int tx = tid & 15;       // col group 0..15
    const int ty = tid >> 4;       // row group 0..15
    const int bm = blockIdx.y;
    const int bn = blockIdx.x;

    const float* Xb = X + (size_t)(bm * 128) * Dc;
    const float* Wb = W + bn * 128;

    float acc[8][8];
#pragma unroll
    for (int i = 0; i < 8; i++)
#pragma unroll
        for (int j = 0; j < 8; j++) acc[i][j] = 0.f;

    const int arow = tid >> 1;           // 0..127
    const int acol = (tid & 1) * 4;      // 0 or 4
    const int brow = tid >> 5;           // 0..7
    const int bcol = (tid & 31) * 4;     // 0..124

    for (int kb = 0; kb < Dc; kb += 8) {
        float4 av = *(const float4*)(Xb + (size_t)arow * Dc + kb + acol);
        float4 bv = *(const float4*)(Wb + (size_t)(kb + brow) * Dc + bcol);
        __syncthreads();   // previous compute done before overwrite
        As[acol + 0][arow] = av.x;
        As[acol + 1][arow] = av.y;
        As[acol + 2][arow] = av.z;
        As[acol + 3][arow] = av.w;
        *(float4*)&Bs[brow][bcol] = bv;
        __syncthreads();
#pragma unroll
        for (int k = 0; k < 8; k++) {
            float4 a0 = *(const float4*)&As[k][ty * 8];
            float4 a1 = *(const float4*)&As[k][ty * 8 + 4];
            float4 b0 = *(const float4*)&Bs[k][tx * 8];
            float4 b1 = *(const float4*)&Bs[k][tx * 8 + 4];
            float ar[8] = {a0.x, a0.y, a0.z, a0.w, a1.x, a1.y, a1.z, a1.w};
            float br[8] = {b0.x, b0.y, b0.z, b0.w, b1.x, b1.y, b1.z, b1.w};
#pragma unroll
            for (int i = 0; i < 8; i++)
#pragma unroll
                for (int j = 0; j < 8; j++)
                    acc[i][j] += ar[i] * br[j];
        }
    }

    // epilogue with bias
#pragma unroll
    for (int i = 0; i < 8; i++) {
        int m = bm * 128 + ty * 8 + i;
#pragma unroll
        for (int jj = 0; jj < 8; jj += 4) {
            int n = bn * 128 + tx * 8 + jj;
            float4 r;
            r.x = acc[i][jj + 0] + bias[n + 0];
            r.y = acc[i][jj + 1] + bias[n + 1];
            r.z = acc[i][jj + 2] + bias[n + 2];
            r.w = acc[i][jj + 3] + bias[n + 3];
            if (LAYOUT == 0) {
                *(float4*)&C[(size_t)m * Dc + n] = r;
            } else {
                int b = m >> 11, s = m & 2047;
                int h = n >> 6, dk = n & 63;
                *(float4*)&C[(((size_t)(b * Hc + h) * Sc + s) * DKc) + dk] = r;
            }
        }
    }
}

struct QKVArgs {
    const float* X[3];
    const float* W[3];
    const float* bias[3];
};

__global__ __launch_bounds__(256, 2) void gemm_qkv_k(QKVArgs args) {
    __shared__ __align__(16) float As[8][128];
    __shared__ __align__(16) float Bs[8][128];
    int v = blockIdx.z;
    float* O = (v == 0) ? g_Q : (v == 1) ? g_K : g_V;
    gemm_body<1>(args.X[v], args.W[v], args.bias[v], O, As, Bs);
}

__global__ __launch_bounds__(256, 2) void gemm_out_k(
    const float* __restrict__ W, const float* __restrict__ bias, float* __restrict__ C) {
    __shared__ __align__(16) float As[8][128];
    __shared__ __align__(16) float Bs[8][128];
    gemm_body<0>(g_ctx, W, bias, C, As, Bs);
}

// ---------------- attention (flash-style, thread-per-query-row) ----------------
// Faithful to reference: masked (j > i, or padding[b, j]) score = 1e-10 (NOT -inf),
// so every key contributes to the softmax denominator.
#define QT 128
#define JT 16

__global__ __launch_bounds__(128, 1) void attn_k() {
    __shared__ __align__(16) float Ks[JT * DKc];
    __shared__ __align__(16) float Vs[JT * DKc];
    __shared__ float pms[JT];

    const int tid = threadIdx.x;
    const int bh = blockIdx.y;
    const int b = bh / Hc, h = bh % Hc;
    const int qi = blockIdx.x * QT + tid;

    const float* Kb = g_K + (size_t)bh * Sc * DKc;
    const float* Vb = g_V + (size_t)bh * Sc * DKc;

    float q[DKc];
    {
        const float4* qr = (const float4*)(g_Q + (size_t)bh * Sc * DKc + (size_t)qi * DKc);
#pragma unroll
        for (int u = 0; u < 16; u++) {
            float4 t = qr[u];
            q[u * 4 + 0] = t.x; q[u * 4 + 1] = t.y;
            q[u * 4 + 2] = t.z; q[u * 4 + 3] = t.w;
        }
    }
    float acc[DKc];
#pragma unroll
    for (int d = 0; d < DKc; d++) acc[d] = 0.f;
    float mrow = -1e30f, lrow = 0.f;

    for (int j0 = 0; j0 < Sc; j0 += JT) {
        __syncthreads();
        // load K/V tiles: JT*64 = 1024 floats each; 128 threads * 2 float4
#pragma unroll
        for (int u = 0; u < 2; u++) {
            int o = (u * 128 + tid) * 4;
            *(float4*)&Ks[o] = *(const float4*)(Kb + (size_t)j0 * DKc + o);
            *(float4*)&Vs[o] = *(const float4*)(Vb + (size_t)j0 * DKc + o);
        }
        if (tid < JT) pms[tid] = g_pm[b * Sc + j0 + tid];
        __syncthreads();

        float s[JT];
#pragma unroll
        for (int j = 0; j < JT; j++) {
            float s0 = 0.f, s1 = 0.f, s2 = 0.f, s3 = 0.f;
#pragma unroll
            for (int d = 0; d < DKc; d += 4) {
                float4 kv = *(const float4*)&Ks[j * DKc + d];
                s0 += q[d + 0] * kv.x;
                s1 += q[d + 1] * kv.y;
                s2 += q[d + 2] * kv.z;
                s3 += q[d + 3] * kv.w;
            }
            float sc = ((s0 + s1) + (s2 + s3)) * 0.125f;  // / sqrt(64)
            bool masked = ((j0 + j) > qi) || (pms[j] != 0.f);
            s[j] = masked ? 1e-10f : sc;
        }
        // online softmax update
        float mt = mrow;
#pragma unroll
        for (int j = 0; j < JT; j++) mt = fmaxf(mt, s[j]);
        float scale = __expf(mrow - mt);
        float ls = 0.f;
#pragma unroll
        for (int j = 0; j < JT; j++) { s[j] = __expf(s[j] - mt); ls += s[j]; }
        lrow = lrow * scale + ls;
        mrow = mt;
#pragma unroll
        for (int d = 0; d < DKc; d++) acc[d] *= scale;
#pragma unroll
        for (int j = 0; j < JT; j++) {
            float p = s[j];
#pragma unroll
            for (int d = 0; d < DKc; d += 4) {
                float4 vv = *(const float4*)&Vs[j * DKc + d];
                acc[d + 0] += p * vv.x;
                acc[d + 1] += p * vv.y;
                acc[d + 2] += p * vv.z;
                acc[d + 3] += p * vv.w;
            }
        }
    }

    float inv = 1.f / lrow;
    float* outp = g_ctx + ((size_t)(b * Sc + qi)) * Dc + h * DKc;
#pragma unroll
    for (int d = 0; d < DKc; d += 4) {
        float4 r;
        r.x = acc[d + 0] * inv; r.y = acc[d + 1] * inv;
        r.z = acc[d + 2] * inv; r.w = acc[d + 3] * inv;
        *(float4*)&outp[d] = r;
    }
}

// ---------------- launch ----------------
extern "C" void kernel_launch(void* const* d_in, const int* in_sizes, int n_in,
                              void* d_out, int out_size) {
    const float* query = (const float*)d_in[0];
    const float* key   = (const float*)d_in[1];
    const float* value = (const float*)d_in[2];
    const void*  pmask = d_in[3];
    const float* Wq = (const float*)d_in[4];
    const float* bq = (const float*)d_in[5];
    const float* Wk = (const float*)d_in[6];
    const float* bk = (const float*)d_in[7];
    const float* Wv = (const float*)d_in[8];
    const float* bv = (const float*)d_in[9];
    const float* Wo = (const float*)d_in[10];
    const float* bo = (const float*)d_in[11];
    float* out = (float*)d_out;

    detect_mask_k<<<1, 256>>>((const unsigned int*)pmask);
    expand_mask_k<<<(Bc * Sc + 255) / 256, 256>>>(pmask);

    QKVArgs args;
    args.X[0] = query; args.X[1] = key; args.X[2] = value;
    args.W[0] = Wq;    args.W[1] = Wk;  args.W[2] = Wv;
    args.bias[0] = bq; args.bias[1] = bk; args.bias[2] = bv;

    dim3 gQKV(Dc / 128, Mc / 128, 3);   // (8, 32, 3)
    gemm_qkv_k<<<gQKV, 256>>>(args);

    dim3 gAttn(Sc / QT, Bc * Hc);       // (16, 32)
    attn_k<<<gAttn, 128>>>();

    dim3 gOut(Dc / 128, Mc / 128);      // (8, 32)
    gemm_out_k<<<gOut, 256>>>(Wo, bo, out);
}

// round 4
// speedup vs baseline: 2.5843x; 2.5843x over previous
#include <cuda_runtime.h>
#include <cuda_bf16.h>
#include <cstdint>

// Problem constants
#define Bc 2
#define Sc 2048
#define Dc 1024
#define Hc 16
#define DKc 64
#define Mc (Bc*Sc)   // 4096

// ---------------- scratch (no allocations allowed) ----------------
// bf16 hi/lo splits of inputs and weights
__device__ __nv_bfloat16 g_Xh[3][Mc*Dc];
__device__ __nv_bfloat16 g_Xl[3][Mc*Dc];
__device__ __nv_bfloat16 g_Wh[4][Dc*Dc];
__device__ __nv_bfloat16 g_Wl[4][Dc*Dc];
// projected q/k/v in [B,H,S,DK] layout, split
__device__ __nv_bfloat16 g_Qh[Mc*Dc], g_Ql[Mc*Dc];
__device__ __nv_bfloat16 g_Kh[Mc*Dc], g_Kl[Mc*Dc];
__device__ __nv_bfloat16 g_Vh[Mc*Dc], g_Vl[Mc*Dc];
// attention context [B,S,D], split
__device__ __nv_bfloat16 g_Ch[Mc*Dc], g_Cl[Mc*Dc];
__device__ float g_pm[Bc*Sc];
__device__ int   g_mask_mode;

// ---------------- helpers ----------------
__device__ __forceinline__ uint32_t smem_u32(const void* p) {
    return (uint32_t)__cvta_generic_to_shared(p);
}

#define MMA(c, a, b0, b1)                                                     \
    asm volatile(                                                             \
        "mma.sync.aligned.m16n8k16.row.col.f32.bf16.bf16.f32 "                \
        "{%0,%1,%2,%3},{%4,%5,%6,%7},{%8,%9},{%0,%1,%2,%3};\n"                \
        : "+f"((c)[0]), "+f"((c)[1]), "+f"((c)[2]), "+f"((c)[3])              \
        : "r"((a)[0]), "r"((a)[1]), "r"((a)[2]), "r"((a)[3]),                 \
          "r"(b0), "r"(b1));

#define LDMX4(r, addr)                                                        \
    asm volatile("ldmatrix.sync.aligned.m8n8.x4.shared.b16 {%0,%1,%2,%3}, [%4];" \
        : "=r"((r)[0]), "=r"((r)[1]), "=r"((r)[2]), "=r"((r)[3]) : "r"(addr));

#define LDMX4T(r, addr)                                                       \
    asm volatile("ldmatrix.sync.aligned.m8n8.x4.trans.shared.b16 {%0,%1,%2,%3}, [%4];" \
        : "=r"((r)[0]), "=r"((r)[1]), "=r"((r)[2]), "=r"((r)[3]) : "r"(addr));

__device__ __forceinline__ uint32_t packh2(float a, float b) {
    __nv_bfloat162 t;
    t.x = __float2bfloat16(a);
    t.y = __float2bfloat16(b);
    return *reinterpret_cast<uint32_t*>(&t);
}
__device__ __forceinline__ uint32_t packl2(float a, float b) {
    float ra = a - __bfloat162float(__float2bfloat16(a));
    float rb = b - __bfloat162float(__float2bfloat16(b));
    return packh2(ra, rb);
}

// ---------------- padding-mask dtype sniffing ----------------
__global__ void detect_mask_k(const unsigned int* __restrict__ mm) {
    __shared__ int okInt, okFloat;
    if (threadIdx.x == 0) { okInt = 1; okFloat = 1; }
    __syncthreads();
    for (int i = threadIdx.x; i < 1024; i += blockDim.x) {
        unsigned int v = mm[i];
        if (v > 1u) okInt = 0;
        if (v != 0u && v != 0x3F800000u) okFloat = 0;
    }
    __syncthreads();
    if (threadIdx.x == 0)
        g_mask_mode = okInt ? 1 : (okFloat ? 2 : 0);
}

__global__ void expand_mask_k(const void* __restrict__ mraw) {
    int i = blockIdx.x * blockDim.x + threadIdx.x;
    if (i >= Bc * Sc) return;
    int mode = g_mask_mode;
    float v;
    if (mode == 1)       v = (((const int*)mraw)[i] != 0) ? 1.f : 0.f;
    else if (mode == 2)  v = (((const float*)mraw)[i] != 0.f) ? 1.f : 0.f;
    else                 v = (((const unsigned char*)mraw)[i] != 0) ? 1.f : 0.f;
    g_pm[i] = v;
}

// ---------------- fp32 -> bf16 hi/lo split ----------------
// id 0..2 -> g_Xh/g_Xl[id] (activations), id 3..6 -> g_Wh/g_Wl[id-3] (weights)
__global__ void split_k(const float* __restrict__ x, int id, int n4) {
    int i = blockIdx.x * blockDim.x + threadIdx.x;
    if (i >= n4) return;
    __nv_bfloat16 *ph, *pl;
    if (id < 3) { ph = g_Xh[id]; pl = g_Xl[id]; }
    else        { ph = g_Wh[id - 3]; pl = g_Wl[id - 3]; }
    float4 v = ((const float4*)x)[i];
    float a[4] = {v.x, v.y, v.z, v.w};
    __nv_bfloat162 h0, h1, l0, l1;
    h0.x = __float2bfloat16(a[0]); h0.y = __float2bfloat16(a[1]);
    h1.x = __float2bfloat16(a[2]); h1.y = __float2bfloat16(a[3]);
    l0.x = __float2bfloat16(a[0] - __bfloat162float(h0.x));
    l0.y = __float2bfloat16(a[1] - __bfloat162float(h0.y));
    l1.x = __float2bfloat16(a[2] - __bfloat162float(h1.x));
    l1.y = __float2bfloat16(a[3] - __bfloat162float(h1.y));
    ((__nv_bfloat162*)ph)[i * 2]     = h0;
    ((__nv_bfloat162*)ph)[i * 2 + 1] = h1;
    ((__nv_bfloat162*)pl)[i * 2]     = l0;
    ((__nv_bfloat162*)pl)[i * 2 + 1] = l1;
}

// ---------------- bf16 split-GEMM: C = A*B + bias ----------------
// 128x128 block tile, 8 warps (2x4), BK=32, 3 MMAs per fragment pair
// mode 0..2 (QKV): A=g_Xh/l[mode], B=g_Wh/l[mode], out -> split bf16 [B,H,S,DK]
// mode 3 (out-proj): A=g_Ch/l, B=g_Wh/l[3], out -> fp32 Cf [Mc,Dc]
struct GemmBias { const float* b[4]; };

__global__ __launch_bounds__(256) void gemm_k(GemmBias gb, int mode_in, float* Cf) {
    const int mode = (mode_in < 0) ? (int)blockIdx.z : mode_in;
    const __nv_bfloat16 *Ah, *Al, *Bh, *Bl;
    __nv_bfloat16 *Oh = nullptr, *Ol = nullptr;
    if (mode < 3) {
        Ah = g_Xh[mode]; Al = g_Xl[mode];
        Bh = g_Wh[mode]; Bl = g_Wl[mode];
        Oh = (mode == 0) ? g_Qh : (mode == 1) ? g_Kh : g_Vh;
        Ol = (mode == 0) ? g_Ql : (mode == 1) ? g_Kl : g_Vl;
    } else {
        Ah = g_Ch; Al = g_Cl; Bh = g_Wh[3]; Bl = g_Wl[3];
    }
    const float* bias = gb.b[mode];

    // padded smem: A rows stride 56 bf16 (112B, 16B-mult, conflict-free),
    // B rows stride 136 bf16 (272B)
    __shared__ __align__(16) __nv_bfloat16 sAh[128 * 56], sAl[128 * 56];
    __shared__ __align__(16) __nv_bfloat16 sBh[32 * 136], sBl[32 * 136];

    const int tid = threadIdx.x;
    const int lane = tid & 31;
    const int wid = tid >> 5;
    const int wm = wid >> 2, wn = wid & 3;     // 2 x 4 warp grid
    const int g = lane >> 2, tg = lane & 3;
    const int sub = lane >> 3, rr = lane & 7;
    const int mBase = blockIdx.y * 128, nBase = blockIdx.x * 128;

    float acc[4][4][4];
#pragma unroll
    for (int i = 0; i < 4; i++)
#pragma unroll
        for (int j = 0; j < 4; j++)
#pragma unroll
            for (int k = 0; k < 4; k++) acc[i][j][k] = 0.f;

    uint4 ra[2], ral[2], rb[2], rbl[2];

    // prefetch tile kb into registers
#define GLOAD(kb)                                                              \
    {                                                                          \
        _Pragma("unroll")                                                      \
        for (int i = 0; i < 2; i++) {                                          \
            int c = tid * 2 + i;                                               \
            int arow = c >> 2, acol = (c & 3) * 8;                             \
            size_t aoff = (size_t)(mBase + arow) * Dc + (kb) * 32 + acol;      \
            ra[i]  = *(const uint4*)(Ah + aoff);                               \
            ral[i] = *(const uint4*)(Al + aoff);                               \
            int brow = c >> 4, bcol = (c & 15) * 8;                            \
            size_t boff = (size_t)((kb) * 32 + brow) * Dc + nBase + bcol;      \
            rb[i]  = *(const uint4*)(Bh + boff);                               \
            rbl[i] = *(const uint4*)(Bl + boff);                               \
        }                                                                      \
    }

    GLOAD(0);
    for (int kb = 0; kb < Dc / 32; kb++) {
        __syncthreads();
#pragma unroll
        for (int i = 0; i < 2; i++) {
            int c = tid * 2 + i;
            int arow = c >> 2, acol = (c & 3) * 8;
            *(uint4*)(sAh + arow * 56 + acol) = ra[i];
            *(uint4*)(sAl + arow * 56 + acol) = ral[i];
            int brow = c >> 4, bcol = (c & 15) * 8;
            *(uint4*)(sBh + brow * 136 + bcol) = rb[i];
            *(uint4*)(sBl + brow * 136 + bcol) = rbl[i];
        }
        __syncthreads();
        if (kb + 1 < Dc / 32) GLOAD(kb + 1);

#pragma unroll
        for (int ks = 0; ks < 2; ks++) {
            uint32_t fah[4][4], fal[4][4];
#pragma unroll
            for (int mf = 0; mf < 4; mf++) {
                int arow = wm * 64 + mf * 16 + (sub & 1) * 8 + rr;
                int acol = ks * 16 + (sub >> 1) * 8;
                LDMX4(fah[mf], smem_u32(sAh + arow * 56 + acol));
                LDMX4(fal[mf], smem_u32(sAl + arow * 56 + acol));
            }
            uint32_t fbh[2][4], fbl[2][4];
#pragma unroll
            for (int nb = 0; nb < 2; nb++) {
                int brow = ks * 16 + (sub & 1) * 8 + rr;
                int bcol = wn * 32 + nb * 16 + (sub >> 1) * 8;
                LDMX4T(fbh[nb], smem_u32(sBh + brow * 136 + bcol));
                LDMX4T(fbl[nb], smem_u32(sBl + brow * 136 + bcol));
            }
#pragma unroll
            for (int mf = 0; mf < 4; mf++)
#pragma unroll
                for (int nf = 0; nf < 4; nf++) {
                    uint32_t b0h = fbh[nf >> 1][(nf & 1) * 2];
                    uint32_t b1h = fbh[nf >> 1][(nf & 1) * 2 + 1];
                    uint32_t b0l = fbl[nf >> 1][(nf & 1) * 2];
                    uint32_t b1l = fbl[nf >> 1][(nf & 1) * 2 + 1];
                    MMA(acc[mf][nf], fah[mf], b0h, b1h);
                    MMA(acc[mf][nf], fah[mf], b0l, b1l);
                    MMA(acc[mf][nf], fal[mf], b0h, b1h);
                }
        }
    }

    // epilogue
#pragma unroll
    for (int mf = 0; mf < 4; mf++) {
        int r0 = mBase + wm * 64 + mf * 16 + g;
        int r1 = r0 + 8;
#pragma unroll
        for (int nf = 0; nf < 4; nf++) {
            int n = nBase + wn * 32 + nf * 8 + tg * 2;
            float bv0 = bias[n], bv1 = bias[n + 1];
            float v00 = acc[mf][nf][0] + bv0, v01 = acc[mf][nf][1] + bv1;
            float v10 = acc[mf][nf][2] + bv0, v11 = acc[mf][nf][3] + bv1;
            if (mode == 3) {
                *(float2*)(Cf + (size_t)r0 * Dc + n) = make_float2(v00, v01);
                *(float2*)(Cf + (size_t)r1 * Dc + n) = make_float2(v10, v11);
            } else {
                int h = n >> 6, dk = n & 63;
#pragma unroll
                for (int p = 0; p < 2; p++) {
                    int r = p ? r1 : r0;
                    float a0 = p ? v10 : v00, a1 = p ? v11 : v01;
                    int b = r >> 11, s = r & 2047;
                    size_t idx = (((size_t)(b * Hc + h)) * Sc + s) * DKc + dk;
                    *(uint32_t*)(Oh + idx) = packh2(a0, a1);
                    *(uint32_t*)(Ol + idx) = packl2(a0, a1);
                }
            }
        }
    }
}

// ---------------- tensor-core flash attention ----------------
// CTA: one (b,h), 64 query rows; 4 warps, each owns 16 rows.
// Masked score = 1e-10 (reference-faithful), scores bounded -> no max tracking;
// PV accumulates monotonically in registers across all KV tiles.
__global__ __launch_bounds__(128) void attn_k() {
    __shared__ __align__(16) __nv_bfloat16 sKh[64 * 72], sKl[64 * 72];
    __shared__ __align__(16) __nv_bfloat16 sVh[64 * 72], sVl[64 * 72];
    __shared__ float pms[64];

    const int tid = threadIdx.x;
    const int lane = tid & 31;
    const int wid = tid >> 5;
    const int g = lane >> 2, tg = lane & 3;
    const int sub = lane >> 3, rr = lane & 7;
    const int bh = blockIdx.y, b = bh >> 4, h = bh & 15;
    const int q0 = blockIdx.x * 64;
    const size_t base = (size_t)bh * Sc * DKc;

    // stage Q through sK buffers, extract A-fragments to registers
    uint32_t qh[4][4], ql[4][4];
    for (int c = tid; c < 64 * 8; c += 128) {
        int row = c >> 3, col = (c & 7) * 8;
        size_t off = base + (size_t)(q0 + row) * DKc + col;
        *(uint4*)(sKh + row * 72 + col) = *(const uint4*)(g_Qh + off);
        *(uint4*)(sKl + row * 72 + col) = *(const uint4*)(g_Ql + off);
    }
    __syncthreads();
#pragma unroll
    for (int kb = 0; kb < 4; kb++) {
        int arow = wid * 16 + (sub & 1) * 8 + rr;
        int acol = kb * 16 + (sub >> 1) * 8;
        LDMX4(qh[kb], smem_u32(sKh + arow * 72 + acol));
        LDMX4(ql[kb], smem_u32(sKl + arow * 72 + acol));
    }

    float o[8][4];
#pragma unroll
    for (int i = 0; i < 8; i++)
#pragma unroll
        for (int k = 0; k < 4; k++) o[i][k] = 0.f;
    float sum0 = 0.f, sum1 = 0.f;
    const int row0 = q0 + wid * 16 + g, row1 = row0 + 8;

    for (int kv0 = 0; kv0 < Sc; kv0 += 64) {
        __syncthreads();
        for (int c = tid; c < 64 * 8; c += 128) {
            int row = c >> 3, col = (c & 7) * 8;
            size_t off = base + (size_t)(kv0 + row) * DKc + col;
            *(uint4*)(sKh + row * 72 + col) = *(const uint4*)(g_Kh + off);
            *(uint4*)(sKl + row * 72 + col) = *(const uint4*)(g_Kl + off);
            *(uint4*)(sVh + row * 72 + col) = *(const uint4*)(g_Vh + off);
            *(uint4*)(sVl + row * 72 + col) = *(const uint4*)(g_Vl + off);
        }
        if (tid < 64) pms[tid] = g_pm[b * Sc + kv0 + tid];
        __syncthreads();

        // S = Q K^T  (split, 3-term)
        float s[8][4];
#pragma unroll
        for (int i = 0; i < 8; i++)
#pragma unroll
            for (int k = 0; k < 4; k++) s[i][k] = 0.f;
#pragma unroll
        for (int jj = 0; jj < 4; jj++) {
#pragma unroll
            for (int kb = 0; kb < 4; kb++) {
                uint32_t bKh[4], bKl[4];
                int krow = jj * 16 + (sub >> 1) * 8 + rr;
                int kcol = kb * 16 + (sub & 1) * 8;
                LDMX4(bKh, smem_u32(sKh + krow * 72 + kcol));
                LDMX4(bKl, smem_u32(sKl + krow * 72 + kcol));
                MMA(s[2 * jj],     qh[kb], bKh[0], bKh[1]);
                MMA(s[2 * jj],     qh[kb], bKl[0], bKl[1]);
                MMA(s[2 * jj],     ql[kb], bKh[0], bKh[1]);
                MMA(s[2 * jj + 1], qh[kb], bKh[2], bKh[3]);
                MMA(s[2 * jj + 1], qh[kb], bKl[2], bKl[3]);
                MMA(s[2 * jj + 1], ql[kb], bKh[2], bKh[3]);
            }
        }

        // mask + exp, re-pack as P A-fragments (register-to-register)
        uint32_t ph[4][4], pl[4][4];
#pragma unroll
        for (int j = 0; j < 8; j++) {
            int cg = kv0 + j * 8 + tg * 2;
            float2 mv = *(float2*)&pms[j * 8 + tg * 2];
            float sc0 = (cg     > row0 || mv.x != 0.f) ? 1e-10f : s[j][0] * 0.125f;
            float sc1 = (cg + 1 > row0 || mv.y != 0.f) ? 1e-10f : s[j][1] * 0.125f;
            float sc2 = (cg     > row1 || mv.x != 0.f) ? 1e-10f : s[j][2] * 0.125f;
            float sc3 = (cg + 1 > row1 || mv.y != 0.f) ? 1e-10f : s[j][3] * 0.125f;
            float e0 = __expf(sc0), e1 = __expf(sc1);
            float e2 = __expf(sc2), e3 = __expf(sc3);
            sum0 += e0 + e1;
            sum1 += e2 + e3;
            int t = j >> 1;
            if ((j & 1) == 0) {
                ph[t][0] = packh2(e0, e1); ph[t][1] = packh2(e2, e3);
                pl[t][0] = packl2(e0, e1); pl[t][1] = packl2(e2, e3);
            } else {
                ph[t][2] = packh2(e0, e1); ph[t][3] = packh2(e2, e3);
                pl[t][2] = packl2(e0, e1); pl[t][3] = packl2(e2, e3);
            }
        }

        // O += P V  (split, 3-term)
#pragma unroll
        for (int dd = 0; dd < 4; dd++) {
#pragma unroll
            for (int t = 0; t < 4; t++) {
                uint32_t vh_[4], vl_[4];
                int vrow = t * 16 + (sub & 1) * 8 + rr;
                int vcol = dd * 16 + (sub >> 1) * 8;
                LDMX4T(vh_, smem_u32(sVh + vrow * 72 + vcol));
                LDMX4T(vl_, smem_u32(sVl + vrow * 72 + vcol));
                MMA(o[2 * dd],     ph[t], vh_[0], vh_[1]);
                MMA(o[2 * dd],     ph[t], vl_[0], vl_[1]);
                MMA(o[2 * dd],     pl[t], vh_[0], vh_[1]);
                MMA(o[2 * dd + 1], ph[t], vh_[2], vh_[3]);
                MMA(o[2 * dd + 1], ph[t], vl_[2], vl_[3]);
                MMA(o[2 * dd + 1], pl[t], vh_[2], vh_[3]);
            }
        }
    }

    // rowsum reduce over the 4 lanes sharing a row (tg bits)
    sum0 += __shfl_xor_sync(0xFFFFFFFFu, sum0, 1);
    sum0 += __shfl_xor_sync(0xFFFFFFFFu, sum0, 2);
    sum1 += __shfl_xor_sync(0xFFFFFFFFu, sum1, 1);
    sum1 += __shfl_xor_sync(0xFFFFFFFFu, sum1, 2);
    float inv0 = 1.f / sum0, inv1 = 1.f / sum1;

#pragma unroll
    for (int nf = 0; nf < 8; nf++) {
        int dk = nf * 8 + tg * 2;
        float v00 = o[nf][0] * inv0, v01 = o[nf][1] * inv0;
        float v10 = o[nf][2] * inv1, v11 = o[nf][3] * inv1;
        size_t i0 = ((size_t)(b * Sc + row0)) * Dc + h * DKc + dk;
        size_t i1 = ((size_t)(b * Sc + row1)) * Dc + h * DKc + dk;
        *(uint32_t*)(g_Ch + i0) = packh2(v00, v01);
        *(uint32_t*)(g_Cl + i0) = packl2(v00, v01);
        *(uint32_t*)(g_Ch + i1) = packh2(v10, v11);
        *(uint32_t*)(g_Cl + i1) = packl2(v10, v11);
    }
}

// ---------------- launch ----------------
extern "C" void kernel_launch(void* const* d_in, const int* in_sizes, int n_in,
                              void* d_out, int out_size) {
    const float* query = (const float*)d_in[0];
    const float* key   = (const float*)d_in[1];
    const float* value = (const float*)d_in[2];
    const void*  pmask = d_in[3];
    const float* Wq = (const float*)d_in[4];
    const float* bq = (const float*)d_in[5];
    const float* Wk = (const float*)d_in[6];
    const float* bk = (const float*)d_in[7];
    const float* Wv = (const float*)d_in[8];
    const float* bv = (const float*)d_in[9];
    const float* Wo = (const float*)d_in[10];
    const float* bo = (const float*)d_in[11];
    float* out = (float*)d_out;

    detect_mask_k<<<1, 256>>>((const unsigned int*)pmask);
    expand_mask_k<<<(Bc * Sc + 255) / 256, 256>>>(pmask);

    // hi/lo splits
    const int nAct4 = Mc * Dc / 4;   // 1M float4
    const int nW4   = Dc * Dc / 4;   // 256K float4
    split_k<<<(nAct4 + 255) / 256, 256>>>(query, 0, nAct4);
    split_k<<<(nAct4 + 255) / 256, 256>>>(key,   1, nAct4);
    split_k<<<(nAct4 + 255) / 256, 256>>>(value, 2, nAct4);
    split_k<<<(nW4 + 255) / 256, 256>>>(Wq, 3, nW4);
    split_k<<<(nW4 + 255) / 256, 256>>>(Wk, 4, nW4);
    split_k<<<(nW4 + 255) / 256, 256>>>(Wv, 5, nW4);
    split_k<<<(nW4 + 255) / 256, 256>>>(Wo, 6, nW4);

    GemmBias gb;
    gb.b[0] = bq; gb.b[1] = bk; gb.b[2] = bv; gb.b[3] = bo;

    dim3 gQKV(Dc / 128, Mc / 128, 3);   // (8, 32, 3)
    gemm_k<<<gQKV, 256>>>(gb, -1, nullptr);

    dim3 gAttn(Sc / 64, Bc * Hc);       // (32, 32)
    attn_k<<<gAttn, 128>>>();

    dim3 gOut(Dc / 128, Mc / 128);      // (8, 32)
    gemm_k<<<gOut, 256>>>(gb, 3, out);
}